// round 2
// baseline (speedup 1.0000x reference)
#include <cuda_runtime.h>

// Problem constants
#define B_    16
#define D_    256
#define HW_   1024            // 32*32
#define N_TOT 16384           // 16 * 1024 vectors
#define K_TOT 8192            // codebook entries
#define ZQ_ELEMS 4194304      // 16*256*32*32

#define KSPLIT 8              // split-K slices for the argmin GEMM

// ---- device scratch (no allocations allowed) ----
__device__ float g_cbnorm[K_TOT];
__device__ float g_znorm[N_TOT];
__device__ float g_bestval[KSPLIT * N_TOT];
__device__ int   g_bestidx[KSPLIT * N_TOT];
__device__ int   g_idx[N_TOT];
__device__ float g_partial[ZQ_ELEMS / 256];   // 16384 block partial sums

// ============================================================
// 1) codebook squared norms (fp64 accumulate -> fp32)
// ============================================================
__global__ void cbnorm_kernel(const float* __restrict__ cb) {
    int warp = threadIdx.x >> 5;
    int lane = threadIdx.x & 31;
    int k = blockIdx.x * 8 + warp;           // 1024 blocks * 8 warps = 8192
    const float4* row = (const float4*)(cb + (size_t)k * D_);  // 64 float4
    double s = 0.0;
    #pragma unroll
    for (int i = lane; i < 64; i += 32) {
        float4 v = row[i];
        s += (double)v.x * v.x + (double)v.y * v.y
           + (double)v.z * v.z + (double)v.w * v.w;
    }
    #pragma unroll
    for (int off = 16; off > 0; off >>= 1)
        s += __shfl_xor_sync(0xffffffffu, s, off);
    if (lane == 0) g_cbnorm[k] = (float)s;
}

// ============================================================
// 1b) z squared norms per vector (fp64 accumulate -> fp32).
//     One thread per n; consecutive threads hit consecutive hw
//     so each channel pass is fully coalesced.
// ============================================================
__global__ void znorm_kernel(const float* __restrict__ z) {
    int n = blockIdx.x * 256 + threadIdx.x;  // 64 blocks * 256
    int b  = n >> 10;
    int hw = n & 1023;
    const float* p = z + (size_t)b * (D_ * HW_) + hw;
    double s = 0.0;
    #pragma unroll 8
    for (int c = 0; c < D_; c++) {
        float v = p[(size_t)c * HW_];
        s += (double)v * v;
    }
    g_znorm[n] = (float)s;
}

// ============================================================
// 2) argmin GEMM: tile 128(n) x 128(k), 8x8 per thread, fp32.
//    Score emulates the reference's fp32 rounding exactly:
//       q = fl( fl(zn + ek) - fl(2*dot) )
//    (2*dot is exact in fp32, so fmaf(-2,dot,r) == r - fl(2*dot))
//    Argmin with lowest-index tie-break, matching jnp.argmin.
// ============================================================
__global__ __launch_bounds__(256, 2)
void argmin_gemm(const float* __restrict__ z, const float* __restrict__ cb) {
    __shared__ float As[16][128];
    __shared__ float Bs[16][128];

    const int tid = threadIdx.x;
    const int tx = tid & 15;
    const int ty = tid >> 4;

    const int n0  = blockIdx.x * 128;
    const int b   = n0 >> 10;          // 128 | 1024 so one batch per block
    const int hw0 = n0 & 1023;
    const float* zb = z + (size_t)b * (D_ * HW_) + hw0;

    const int k_begin = blockIdx.y * (K_TOT / KSPLIT);
    const int k_tiles = (K_TOT / KSPLIT) / 128;

    // per-thread row indices and their z-norms
    float znr[8];
    #pragma unroll
    for (int i = 0; i < 8; i++) {
        int row = (i < 4) ? (ty * 4 + i) : (64 + ty * 4 + (i - 4));
        znr[i] = g_znorm[n0 + row];
    }

    float best[8];
    int   bidx[8];
    #pragma unroll
    for (int i = 0; i < 8; i++) { best[i] = 3.4e38f; bidx[i] = 0; }

    float acc[8][8];

    for (int kt = 0; kt < k_tiles; ++kt) {
        const int k0 = k_begin + kt * 128;
        #pragma unroll
        for (int i = 0; i < 8; i++)
            #pragma unroll
            for (int j = 0; j < 8; j++) acc[i][j] = 0.f;

        for (int d0 = 0; d0 < D_; d0 += 16) {
            // load A tile: 16 d x 128 n  (512 float4, 2 per thread)
            #pragma unroll
            for (int r = 0; r < 2; r++) {
                int idx = tid + r * 256;
                int dd = idx >> 5;
                int n4 = idx & 31;
                float4 v = *(const float4*)(zb + (size_t)(d0 + dd) * HW_ + n4 * 4);
                *(float4*)&As[dd][n4 * 4] = v;
            }
            // load B tile: 128 k x 16 d, transposed into Bs[d][k]
            #pragma unroll
            for (int r = 0; r < 2; r++) {
                int idx = tid + r * 256;
                int kk = idx >> 2;
                int d4 = idx & 3;
                float4 v = *(const float4*)(cb + (size_t)(k0 + kk) * D_ + d0 + d4 * 4);
                Bs[d4 * 4 + 0][kk] = v.x;
                Bs[d4 * 4 + 1][kk] = v.y;
                Bs[d4 * 4 + 2][kk] = v.z;
                Bs[d4 * 4 + 3][kk] = v.w;
            }
            __syncthreads();

            #pragma unroll
            for (int dd = 0; dd < 16; ++dd) {
                float4 a0 = *(const float4*)&As[dd][ty * 4];
                float4 a1 = *(const float4*)&As[dd][64 + ty * 4];
                float4 b0 = *(const float4*)&Bs[dd][tx * 4];
                float4 b1 = *(const float4*)&Bs[dd][64 + tx * 4];
                float av[8] = {a0.x, a0.y, a0.z, a0.w, a1.x, a1.y, a1.z, a1.w};
                float bv[8] = {b0.x, b0.y, b0.z, b0.w, b1.x, b1.y, b1.z, b1.w};
                #pragma unroll
                for (int i = 0; i < 8; i++)
                    #pragma unroll
                    for (int j = 0; j < 8; j++)
                        acc[i][j] = fmaf(av[i], bv[j], acc[i][j]);
            }
            __syncthreads();
        }

        // Exact-fp32-emulated score; kc ascends within a thread across
        // j and kt, so strict < keeps the lowest index on exact ties.
        #pragma unroll
        for (int j = 0; j < 8; j++) {
            int kc = k0 + ((j < 4) ? (tx * 4 + j) : (64 + tx * 4 + (j - 4)));
            float nk = g_cbnorm[kc];
            #pragma unroll
            for (int i = 0; i < 8; i++) {
                float r = __fadd_rn(znr[i], nk);        // fl(zn + ek)
                float s = fmaf(-2.f, acc[i][j], r);     // fl(r - 2*dot)
                if (s < best[i]) { best[i] = s; bidx[i] = kc; }
            }
        }
    }

    // reduce across the 16 tx-lanes holding the same rows
    #pragma unroll
    for (int i = 0; i < 8; i++) {
        float v = best[i];
        int   kv = bidx[i];
        #pragma unroll
        for (int off = 8; off > 0; off >>= 1) {
            float ov = __shfl_xor_sync(0xffffffffu, v, off);
            int   oi = __shfl_xor_sync(0xffffffffu, kv, off);
            if (ov < v || (ov == v && oi < kv)) { v = ov; kv = oi; }
        }
        if (tx == 0) {
            int row = (i < 4) ? (ty * 4 + i) : (64 + ty * 4 + (i - 4));
            int slot = blockIdx.y * N_TOT + n0 + row;
            g_bestval[slot] = v;
            g_bestidx[slot] = kv;
        }
    }
}

// ============================================================
// 3) combine split-K candidates; emit final idx (+float copy to out)
// ============================================================
__global__ void combine_kernel(float* __restrict__ out_idx) {
    int n = blockIdx.x * 256 + threadIdx.x;
    if (n >= N_TOT) return;
    float bv = g_bestval[n];
    int   bi = g_bestidx[n];
    #pragma unroll
    for (int s = 1; s < KSPLIT; s++) {
        float v = g_bestval[s * N_TOT + n];
        int   i = g_bestidx[s * N_TOT + n];
        if (v < bv || (v == bv && i < bi)) { bv = v; bi = i; }
    }
    g_idx[n] = bi;
    out_idx[n] = (float)bi;
}

// ============================================================
// 4) gather z_q (STE forward value == codebook[idx]) + per-block
//    partial sums of (z_q - zp)^2
// ============================================================
__global__ void gather_loss(const float* __restrict__ z,
                            const float* __restrict__ cb,
                            float* __restrict__ out_zq) {
    __shared__ float red[256];
    int i = blockIdx.x * 256 + threadIdx.x;  // over ZQ_ELEMS, bchw order
    int hw = i & 1023;
    int c  = (i >> 10) & 255;
    int b  = i >> 18;
    int n  = (b << 10) + hw;
    int k  = g_idx[n];
    float q  = cb[(size_t)k * D_ + c];
    float zv = z[i];
    out_zq[i] = q;
    float d = q - zv;
    red[threadIdx.x] = d * d;
    __syncthreads();
    #pragma unroll
    for (int off = 128; off > 0; off >>= 1) {
        if (threadIdx.x < off) red[threadIdx.x] += red[threadIdx.x + off];
        __syncthreads();
    }
    if (threadIdx.x == 0) g_partial[blockIdx.x] = red[0];
}

// ============================================================
// 5) finalize loss = 1.25 * mean((z_q - zp)^2)   (deterministic)
// ============================================================
__global__ void finalize_loss(float* __restrict__ out_loss) {
    __shared__ double red[1024];
    double s = 0.0;
    for (int i = threadIdx.x; i < ZQ_ELEMS / 256; i += 1024)
        s += (double)g_partial[i];
    red[threadIdx.x] = s;
    __syncthreads();
    #pragma unroll
    for (int off = 512; off > 0; off >>= 1) {
        if (threadIdx.x < off) red[threadIdx.x] += red[threadIdx.x + off];
        __syncthreads();
    }
    if (threadIdx.x == 0)
        out_loss[0] = (float)(1.25 * red[0] / (double)ZQ_ELEMS);
}

// ============================================================
extern "C" void kernel_launch(void* const* d_in, const int* in_sizes, int n_in,
                              void* d_out, int out_size) {
    const float* z  = (const float*)d_in[0];
    const float* cb = (const float*)d_in[1];
    float* out      = (float*)d_out;

    // output layout: [ z_q (4194304) | loss (1) | idx (16384) ]
    float* out_zq   = out;
    float* out_loss = out + ZQ_ELEMS;
    float* out_idx  = out + ZQ_ELEMS + 1;

    cbnorm_kernel<<<K_TOT / 8, 256>>>(cb);
    znorm_kernel<<<N_TOT / 256, 256>>>(z);

    dim3 grid(N_TOT / 128, KSPLIT);
    argmin_gemm<<<grid, 256>>>(z, cb);

    combine_kernel<<<(N_TOT + 255) / 256, 256>>>(out_idx);

    gather_loss<<<ZQ_ELEMS / 256, 256>>>(z, cb, out_zq);

    finalize_loss<<<1, 1024>>>(out_loss);
}

// round 4
// speedup vs baseline: 1.6365x; 1.6365x over previous
#include <cuda_runtime.h>
#include <cuda_bf16.h>
#include <cstdint>

// Problem constants
#define D_    256
#define HW_   1024            // 32*32
#define N_TOT 16384           // 16 * 1024 vectors
#define K_TOT 8192            // codebook entries
#define ZQ_ELEMS 4194304      // 16*256*32*32
#define NTILES 64             // K_TOT / 128 codes per tile

// ---- device scratch (no allocations allowed) ----
__device__ float g_cbnorm[K_TOT];
__device__ float g_znorm[N_TOT];
__device__ int   g_idx[N_TOT];
__device__ float g_partial[ZQ_ELEMS / 256];
__device__ __nv_bfloat16 g_zbf16[N_TOT * D_];    // [n][d] row-major (512B rows)
__device__ __nv_bfloat16 g_cbbf16[K_TOT * D_];   // [k][d] row-major (512B rows)
__device__ int   g_cand[N_TOT * 32];             // 32 candidates per vector

// ---- smem layout for the MMA kernel (dynamic) ----
#define SM_A   0               // 128 rows x 512B (z tile, resident)
#define SM_B   65536           // 2 x 128 rows x 512B (codebook, dbl buf)
#define SM_NK  196608          // 2 x 128 floats (code norms, dbl buf)
#define SM_TOTAL 197632

// ---- PTX helpers (non-'a' target instructions only) ----
__device__ __forceinline__ uint32_t smem_u32(const void* p) {
    uint32_t a;
    asm("{ .reg .u64 t; cvta.to.shared.u64 t, %1; cvt.u32.u64 %0, t; }"
        : "=r"(a) : "l"(p));
    return a;
}
__device__ __forceinline__ void cp_async16(uint32_t dst, const void* src) {
    asm volatile("cp.async.cg.shared.global [%0], [%1], 16;"
                 :: "r"(dst), "l"(src) : "memory");
}
#define CP_COMMIT() asm volatile("cp.async.commit_group;" ::: "memory")
#define CP_WAIT1()  asm volatile("cp.async.wait_group 1;" ::: "memory")
#define CP_WAIT0()  asm volatile("cp.async.wait_group 0;" ::: "memory")

#define LDSM4(r0, r1, r2, r3, addr)                                        \
    asm volatile("ldmatrix.sync.aligned.m8n8.x4.shared.b16 "               \
                 "{%0,%1,%2,%3}, [%4];"                                    \
                 : "=r"(r0), "=r"(r1), "=r"(r2), "=r"(r3) : "r"(addr))

#define MMA16816(d, a, b0, b1)                                             \
    asm volatile("mma.sync.aligned.m16n8k16.row.col.f32.bf16.bf16.f32 "    \
                 "{%0,%1,%2,%3}, {%4,%5,%6,%7}, {%8,%9}, {%0,%1,%2,%3};"   \
                 : "+f"((d)[0]), "+f"((d)[1]), "+f"((d)[2]), "+f"((d)[3])  \
                 : "r"((a)[0]), "r"((a)[1]), "r"((a)[2]), "r"((a)[3]),     \
                   "r"(b0), "r"(b1))

// sorted-insert into a length-4 ascending list (compile-time L)
#define INSERT4(L, sval, kval) do {                                        \
    if ((sval) < cs[L][3]) {                                               \
        float _vs = (sval); int _vi = (kval);                              \
        _Pragma("unroll")                                                  \
        for (int _j = 0; _j < 4; _j++) {                                   \
            if (_vs < cs[L][_j]) {                                         \
                float _tf = cs[L][_j]; int _ti = ci[L][_j];                \
                cs[L][_j] = _vs; ci[L][_j] = _vi; _vs = _tf; _vi = _ti;    \
            }                                                              \
        }                                                                  \
    }                                                                      \
} while (0)

// ============================================================
// prep: codebook squared norms (fp64 accumulate -> fp32)
// ============================================================
__global__ void cbnorm_kernel(const float* __restrict__ cb) {
    int warp = threadIdx.x >> 5;
    int lane = threadIdx.x & 31;
    int k = blockIdx.x * 8 + warp;
    const float4* row = (const float4*)(cb + (size_t)k * D_);
    double s = 0.0;
    #pragma unroll
    for (int i = lane; i < 64; i += 32) {
        float4 v = row[i];
        s += (double)v.x * v.x + (double)v.y * v.y
           + (double)v.z * v.z + (double)v.w * v.w;
    }
    #pragma unroll
    for (int off = 16; off > 0; off >>= 1)
        s += __shfl_xor_sync(0xffffffffu, s, off);
    if (lane == 0) g_cbnorm[k] = (float)s;
}

// ============================================================
// prep: z squared norms per vector
// ============================================================
__global__ void znorm_kernel(const float* __restrict__ z) {
    int n = blockIdx.x * 256 + threadIdx.x;
    int b  = n >> 10;
    int hw = n & 1023;
    const float* p = z + (size_t)b * (D_ * HW_) + hw;
    double s = 0.0;
    #pragma unroll 8
    for (int c = 0; c < D_; c++) {
        float v = p[(size_t)c * HW_];
        s += (double)v * v;
    }
    g_znorm[n] = (float)s;
}

// ============================================================
// prep: codebook fp32 -> bf16
// ============================================================
__global__ void cvt_cb_kernel(const float* __restrict__ cb) {
    int i = blockIdx.x * 256 + threadIdx.x;   // 524288 float4s
    float4 v = ((const float4*)cb)[i];
    __nv_bfloat162 lo = __floats2bfloat162_rn(v.x, v.y);
    __nv_bfloat162 hi = __floats2bfloat162_rn(v.z, v.w);
    uint2 o;
    o.x = *(const uint32_t*)&lo;
    o.y = *(const uint32_t*)&hi;
    ((uint2*)g_cbbf16)[i] = o;
}

// ============================================================
// prep: z [b,c,hw] fp32 -> g_zbf16 [n][c] bf16 (transpose)
// ============================================================
__global__ void cvt_z_kernel(const float* __restrict__ z) {
    __shared__ float t[32][33];
    int b  = blockIdx.z;
    int hw0 = blockIdx.y * 32;
    int c0  = blockIdx.x * 32;
    int tx = threadIdx.x, ty = threadIdx.y;   // 32 x 8
    #pragma unroll
    for (int r = 0; r < 4; r++) {
        int c = c0 + ty + r * 8;
        t[ty + r * 8][tx] = z[((size_t)b * D_ + c) * HW_ + hw0 + tx];
    }
    __syncthreads();
    #pragma unroll
    for (int r = 0; r < 4; r++) {
        int n = b * HW_ + hw0 + ty + r * 8;
        g_zbf16[(size_t)n * D_ + c0 + tx] = __float2bfloat16_rn(t[tx][ty + r * 8]);
    }
}

// ============================================================
// main: bf16 mma.sync candidate GEMM.
// grid = 128 CTAs (128 z-rows each), 256 threads (8 warps, 4m x 2n).
// Warp tile 32(m) x 64(n); per thread 2 m16 x 8 n8 tiles, 64 accums.
// Per-thread per-row top-4 candidate lists (8 domains x 4 per row).
// ============================================================
__global__ __launch_bounds__(256, 1) void vq_mma_kernel() {
    extern __shared__ __align__(128) char smem[];
    const uint32_t sb = smem_u32(smem);
    const int tid  = threadIdx.x;
    const int lane = tid & 31;
    const int wid  = tid >> 5;
    const int wm   = wid & 3;      // warp row group (0..3)
    const int wn   = wid >> 2;     // warp col group (0..1)
    const int n0   = blockIdx.x * 128;

    // ---- load A (z rows) into smem, swizzled ----
    {
        const char* srcA = (const char*)g_zbf16 + (size_t)n0 * 512;
        #pragma unroll
        for (int j = 0; j < 16; j++) {
            int i = tid + j * 256;              // 4096 16B chunks
            int r = i >> 5, c16 = i & 31;
            uint32_t kb = c16 * 16;
            cp_async16(sb + SM_A + r * 512 + (kb ^ ((r & 7) << 4)),
                       srcA + (size_t)r * 512 + kb);
        }
    }
    // ---- load B tile 0 + norms ----
    {
        const char* srcB = (const char*)g_cbbf16;
        #pragma unroll
        for (int j = 0; j < 16; j++) {
            int i = tid + j * 256;
            int r = i >> 5, c16 = i & 31;
            uint32_t kb = c16 * 16;
            cp_async16(sb + SM_B + r * 512 + (kb ^ ((r & 7) << 4)),
                       srcB + (size_t)r * 512 + kb);
        }
        if (tid < 32)
            cp_async16(sb + SM_NK + tid * 16, (const char*)g_cbnorm + tid * 16);
    }
    CP_COMMIT();

    // per-thread z norms for its 4 rows
    float znr[2][2];
    #pragma unroll
    for (int mt = 0; mt < 2; mt++)
        #pragma unroll
        for (int g = 0; g < 2; g++)
            znr[mt][g] = g_znorm[n0 + wm * 32 + mt * 16 + g * 8 + (lane >> 2)];

    // ldmatrix lane addressing (same scheme for A and B)
    const int lrow8 = ((lane >> 3) & 1) * 8 + (lane & 7);
    const uint32_t kext = (lane >> 4) * 16;
    const uint32_t xorv = (uint32_t)(lane & 7) << 4;
    uint32_t aBase[2];
    #pragma unroll
    for (int mt = 0; mt < 2; mt++)
        aBase[mt] = sb + SM_A + (wm * 32 + mt * 16 + lrow8) * 512;
    uint32_t bOff[4];
    #pragma unroll
    for (int np = 0; np < 4; np++)
        bOff[np] = (wn * 64 + np * 16 + lrow8) * 512;

    // candidate lists: [mt*2+g][4]
    float cs[4][4];
    int   ci[4][4];
    #pragma unroll
    for (int l = 0; l < 4; l++)
        #pragma unroll
        for (int j = 0; j < 4; j++) { cs[l][j] = 3.4e38f; ci[l][j] = 0; }

    for (int t = 0; t < NTILES; t++) {
        const int buf = t & 1;
        // prefetch next B tile into the other buffer
        if (t + 1 < NTILES) {
            const char* srcB = (const char*)g_cbbf16 + (size_t)(t + 1) * 128 * 512;
            uint32_t dst = sb + SM_B + (buf ^ 1) * 65536;
            #pragma unroll
            for (int j = 0; j < 16; j++) {
                int i = tid + j * 256;
                int r = i >> 5, c16 = i & 31;
                uint32_t kb = c16 * 16;
                cp_async16(dst + r * 512 + (kb ^ ((r & 7) << 4)),
                           srcB + (size_t)r * 512 + kb);
            }
            if (tid < 32)
                cp_async16(sb + SM_NK + (buf ^ 1) * 512 + tid * 16,
                           (const char*)(g_cbnorm + (t + 1) * 128) + tid * 16);
            CP_COMMIT();
            CP_WAIT1();
        } else {
            CP_WAIT0();
        }
        __syncthreads();

        // ---- 16 k-steps of mma over D=256 ----
        float acc[2][8][4];
        #pragma unroll
        for (int mt = 0; mt < 2; mt++)
            #pragma unroll
            for (int nt = 0; nt < 8; nt++)
                #pragma unroll
                for (int q = 0; q < 4; q++) acc[mt][nt][q] = 0.f;

        const uint32_t bBase = sb + SM_B + buf * 65536;
        #pragma unroll
        for (int ks = 0; ks < 16; ks++) {
            const uint32_t kb = ks * 32;
            uint32_t a[2][4];
            #pragma unroll
            for (int mt = 0; mt < 2; mt++)
                LDSM4(a[mt][0], a[mt][1], a[mt][2], a[mt][3],
                      aBase[mt] + ((kb + kext) ^ xorv));
            uint32_t b[4][4];
            #pragma unroll
            for (int np = 0; np < 4; np++)
                LDSM4(b[np][0], b[np][1], b[np][2], b[np][3],
                      bBase + bOff[np] + ((kb + kext) ^ xorv));
            #pragma unroll
            for (int mt = 0; mt < 2; mt++)
                #pragma unroll
                for (int nt = 0; nt < 8; nt++)
                    MMA16816(acc[mt][nt], a[mt],
                             b[nt >> 1][nt & 1], b[nt >> 1][2 + (nt & 1)]);
        }

        // ---- epilogue: fold norms, update top-4 lists ----
        {
            const float* nk = (const float*)(smem + SM_NK + buf * 512);
            const int cb0 = wn * 64 + 2 * (lane & 3);
            #pragma unroll
            for (int nt = 0; nt < 8; nt++) {
                int c = cb0 + nt * 8;
                float nk0 = nk[c], nk1 = nk[c + 1];
                int kc = t * 128 + c;
                #pragma unroll
                for (int mt = 0; mt < 2; mt++) {
                    float s;
                    s = fmaf(-2.f, acc[mt][nt][0], znr[mt][0] + nk0);
                    INSERT4(mt * 2 + 0, s, kc);
                    s = fmaf(-2.f, acc[mt][nt][1], znr[mt][0] + nk1);
                    INSERT4(mt * 2 + 0, s, kc + 1);
                    s = fmaf(-2.f, acc[mt][nt][2], znr[mt][1] + nk0);
                    INSERT4(mt * 2 + 1, s, kc);
                    s = fmaf(-2.f, acc[mt][nt][3], znr[mt][1] + nk1);
                    INSERT4(mt * 2 + 1, s, kc + 1);
                }
            }
        }
        __syncthreads();   // lists done; safe to overwrite buf next iter
    }

    // ---- write candidates: per row 8 domains x 4 ----
    const int dom = wn * 4 + (lane & 3);
    #pragma unroll
    for (int mt = 0; mt < 2; mt++)
        #pragma unroll
        for (int g = 0; g < 2; g++) {
            int n = n0 + wm * 32 + mt * 16 + g * 8 + (lane >> 2);
            #pragma unroll
            for (int j = 0; j < 4; j++)
                g_cand[n * 32 + dom * 4 + j] = ci[mt * 2 + g][j];
        }
}

// ============================================================
// exact rescore of 32 candidates per vector, bit-matching the
// reference fp32 quantization:  q = fl(fl(zn+ek) - fl(2*dot)),
// dot = sequential fp32 fmaf over d (identical to the R2 pass).
// ============================================================
__global__ __launch_bounds__(256, 2)
void rescore_kernel(const float* __restrict__ z, const float* __restrict__ cb,
                    float* __restrict__ out_idx) {
    __shared__ float zs[8][D_];
    int w = threadIdx.x >> 5, lane = threadIdx.x & 31;
    int n = blockIdx.x * 8 + w;
    int b = n >> 10, hw = n & 1023;
    const float* zp = z + (size_t)b * (D_ * HW_) + hw;
    for (int d = lane; d < D_; d += 32)
        zs[w][d] = zp[(size_t)d * HW_];
    __syncwarp();
    int k = g_cand[n * 32 + lane];
    const float* cr = cb + (size_t)k * D_;
    float acc = 0.f;
    #pragma unroll 8
    for (int d = 0; d < D_; d++)
        acc = fmaf(zs[w][d], cr[d], acc);
    float r = __fadd_rn(g_znorm[n], g_cbnorm[k]);
    float q = fmaf(-2.f, acc, r);
    int ki = k;
    #pragma unroll
    for (int off = 16; off > 0; off >>= 1) {
        float oq = __shfl_xor_sync(0xffffffffu, q, off);
        int   oi = __shfl_xor_sync(0xffffffffu, ki, off);
        if (oq < q || (oq == q && oi < ki)) { q = oq; ki = oi; }
    }
    if (lane == 0) {
        g_idx[n] = ki;
        out_idx[n] = (float)ki;
    }
}

// ============================================================
// gather z_q + per-block partial sums of (z_q - zp)^2
// ============================================================
__global__ void gather_loss(const float* __restrict__ z,
                            const float* __restrict__ cb,
                            float* __restrict__ out_zq) {
    __shared__ float red[256];
    int i = blockIdx.x * 256 + threadIdx.x;
    int hw = i & 1023;
    int c  = (i >> 10) & 255;
    int b  = i >> 18;
    int n  = (b << 10) + hw;
    int k  = g_idx[n];
    float q  = cb[(size_t)k * D_ + c];
    float zv = z[i];
    out_zq[i] = q;
    float d = q - zv;
    red[threadIdx.x] = d * d;
    __syncthreads();
    #pragma unroll
    for (int off = 128; off > 0; off >>= 1) {
        if (threadIdx.x < off) red[threadIdx.x] += red[threadIdx.x + off];
        __syncthreads();
    }
    if (threadIdx.x == 0) g_partial[blockIdx.x] = red[0];
}

__global__ void finalize_loss(float* __restrict__ out_loss) {
    __shared__ double red[1024];
    double s = 0.0;
    for (int i = threadIdx.x; i < ZQ_ELEMS / 256; i += 1024)
        s += (double)g_partial[i];
    red[threadIdx.x] = s;
    __syncthreads();
    #pragma unroll
    for (int off = 512; off > 0; off >>= 1) {
        if (threadIdx.x < off) red[threadIdx.x] += red[threadIdx.x + off];
        __syncthreads();
    }
    if (threadIdx.x == 0)
        out_loss[0] = (float)(1.25 * red[0] / (double)ZQ_ELEMS);
}

// ============================================================
extern "C" void kernel_launch(void* const* d_in, const int* in_sizes, int n_in,
                              void* d_out, int out_size) {
    const float* z  = (const float*)d_in[0];
    const float* cb = (const float*)d_in[1];
    float* out      = (float*)d_out;

    float* out_zq   = out;
    float* out_loss = out + ZQ_ELEMS;
    float* out_idx  = out + ZQ_ELEMS + 1;

    cudaFuncSetAttribute(vq_mma_kernel,
                         cudaFuncAttributeMaxDynamicSharedMemorySize, SM_TOTAL);

    cbnorm_kernel<<<K_TOT / 8, 256>>>(cb);
    znorm_kernel<<<N_TOT / 256, 256>>>(z);
    cvt_cb_kernel<<<(K_TOT * D_ / 4) / 256, 256>>>(cb);
    cvt_z_kernel<<<dim3(D_ / 32, HW_ / 32, 16), dim3(32, 8)>>>(z);

    vq_mma_kernel<<<N_TOT / 128, 256, SM_TOTAL>>>();

    rescore_kernel<<<N_TOT / 8, 256>>>(z, cb, out_idx);

    gather_loss<<<ZQ_ELEMS / 256, 256>>>(z, cb, out_zq);

    finalize_loss<<<1, 1024>>>(out_loss);
}

// round 5
// speedup vs baseline: 2.9881x; 1.8258x over previous
#include <cuda_runtime.h>
#include <cuda_bf16.h>
#include <cstdint>

// Problem constants
#define D_    256
#define HW_   1024            // 32*32
#define N_TOT 16384           // 16 * 1024 vectors
#define K_TOT 8192            // codebook entries
#define ZQ_ELEMS 4194304      // 16*256*32*32
#define NTILES 64             // K_TOT / 128 codes per tile

// ---- device scratch (no allocations allowed) ----
__device__ float g_cbnorm[K_TOT];
__device__ float g_znorm[N_TOT];
__device__ int   g_idx[N_TOT];
__device__ float g_partial[ZQ_ELEMS / 256];
__device__ __nv_bfloat16 g_zbf16[N_TOT * D_];    // [n][d] row-major (512B rows)
__device__ __nv_bfloat16 g_cbbf16[K_TOT * D_];   // [k][d] row-major (512B rows)
__device__ int   g_cand[N_TOT * 32];             // 32 candidates per vector

// ---- smem layout for the MMA kernel (dynamic) ----
#define SM_A   0               // 128 rows x 512B (z tile, resident)
#define SM_B   65536           // 2 x 128 rows x 512B (codebook, dbl buf)
#define SM_NK  196608          // 2 x 128 floats (code norms, dbl buf)
#define SM_TOTAL 197632

// ---- PTX helpers (non-'a' target instructions only) ----
__device__ __forceinline__ uint32_t smem_u32(const void* p) {
    uint32_t a;
    asm("{ .reg .u64 t; cvta.to.shared.u64 t, %1; cvt.u32.u64 %0, t; }"
        : "=r"(a) : "l"(p));
    return a;
}
__device__ __forceinline__ void cp_async16(uint32_t dst, const void* src) {
    asm volatile("cp.async.cg.shared.global [%0], [%1], 16;"
                 :: "r"(dst), "l"(src) : "memory");
}
#define CP_COMMIT() asm volatile("cp.async.commit_group;" ::: "memory")
#define CP_WAIT1()  asm volatile("cp.async.wait_group 1;" ::: "memory")
#define CP_WAIT0()  asm volatile("cp.async.wait_group 0;" ::: "memory")

#define LDSM4(r0, r1, r2, r3, addr)                                        \
    asm volatile("ldmatrix.sync.aligned.m8n8.x4.shared.b16 "               \
                 "{%0,%1,%2,%3}, [%4];"                                    \
                 : "=r"(r0), "=r"(r1), "=r"(r2), "=r"(r3) : "r"(addr))

#define MMA16816(d, a, b0, b1)                                             \
    asm volatile("mma.sync.aligned.m16n8k16.row.col.f32.bf16.bf16.f32 "    \
                 "{%0,%1,%2,%3}, {%4,%5,%6,%7}, {%8,%9}, {%0,%1,%2,%3};"   \
                 : "+f"((d)[0]), "+f"((d)[1]), "+f"((d)[2]), "+f"((d)[3])  \
                 : "r"((a)[0]), "r"((a)[1]), "r"((a)[2]), "r"((a)[3]),     \
                   "r"(b0), "r"(b1))

// sorted-insert into a length-4 ascending list (compile-time L)
#define INSERT4(L, sval, kval) do {                                        \
    if ((sval) < cs[L][3]) {                                               \
        float _vs = (sval); int _vi = (kval);                              \
        _Pragma("unroll")                                                  \
        for (int _j = 0; _j < 4; _j++) {                                   \
            if (_vs < cs[L][_j]) {                                         \
                float _tf = cs[L][_j]; int _ti = ci[L][_j];                \
                cs[L][_j] = _vs; ci[L][_j] = _vi; _vs = _tf; _vi = _ti;    \
            }                                                              \
        }                                                                  \
    }                                                                      \
} while (0)

// ============================================================
// prep: z squared norms per vector (launch #1)
// ============================================================
__global__ void znorm_kernel(const float* __restrict__ z) {
    int n = blockIdx.x * 256 + threadIdx.x;
    int b  = n >> 10;
    int hw = n & 1023;
    const float* p = z + (size_t)b * (D_ * HW_) + hw;
    double s = 0.0;
    #pragma unroll 8
    for (int c = 0; c < D_; c++) {
        float v = p[(size_t)c * HW_];
        s += (double)v * v;
    }
    g_znorm[n] = (float)s;
}

// ============================================================
// prep: fused codebook norms (fp64) + fp32->bf16 convert (launch #2)
// one warp per code row
// ============================================================
__global__ void cb_prep_kernel(const float* __restrict__ cb) {
    int warp = threadIdx.x >> 5;
    int lane = threadIdx.x & 31;
    int k = blockIdx.x * 8 + warp;
    const float4* row = (const float4*)(cb + (size_t)k * D_);
    float4 v0 = row[lane * 2];
    float4 v1 = row[lane * 2 + 1];
    double s = (double)v0.x * v0.x + (double)v0.y * v0.y
             + (double)v0.z * v0.z + (double)v0.w * v0.w
             + (double)v1.x * v1.x + (double)v1.y * v1.y
             + (double)v1.z * v1.z + (double)v1.w * v1.w;
    #pragma unroll
    for (int off = 16; off > 0; off >>= 1)
        s += __shfl_xor_sync(0xffffffffu, s, off);
    if (lane == 0) g_cbnorm[k] = (float)s;
    // bf16 write: lane covers d [8*lane, 8*lane+8)
    __nv_bfloat162 a = __floats2bfloat162_rn(v0.x, v0.y);
    __nv_bfloat162 b = __floats2bfloat162_rn(v0.z, v0.w);
    __nv_bfloat162 c = __floats2bfloat162_rn(v1.x, v1.y);
    __nv_bfloat162 d = __floats2bfloat162_rn(v1.z, v1.w);
    uint4 o;
    o.x = *(const uint32_t*)&a; o.y = *(const uint32_t*)&b;
    o.z = *(const uint32_t*)&c; o.w = *(const uint32_t*)&d;
    *(uint4*)(g_cbbf16 + (size_t)k * D_ + lane * 8) = o;
}

// ============================================================
// prep: z [b,c,hw] fp32 -> g_zbf16 [n][c] bf16 (transpose) (launch #3)
// ============================================================
__global__ void cvt_z_kernel(const float* __restrict__ z) {
    __shared__ float t[32][33];
    int b  = blockIdx.z;
    int hw0 = blockIdx.y * 32;
    int c0  = blockIdx.x * 32;
    int tx = threadIdx.x, ty = threadIdx.y;   // 32 x 8
    #pragma unroll
    for (int r = 0; r < 4; r++) {
        int c = c0 + ty + r * 8;
        t[ty + r * 8][tx] = z[((size_t)b * D_ + c) * HW_ + hw0 + tx];
    }
    __syncthreads();
    #pragma unroll
    for (int r = 0; r < 4; r++) {
        int n = b * HW_ + hw0 + ty + r * 8;
        g_zbf16[(size_t)n * D_ + c0 + tx] = __float2bfloat16_rn(t[tx][ty + r * 8]);
    }
}

// ============================================================
// main: bf16 mma.sync candidate GEMM (launch #4 -> ncu profiles this).
// grid = 128 CTAs (128 z-rows each), 256 threads (8 warps, 4m x 2n).
// Warp tile 32(m) x 64(n); per thread 2 m16 x 8 n8 tiles, 64 accums.
// Per-thread per-row top-4 candidate lists (8 domains x 4 per row).
// ============================================================
__global__ __launch_bounds__(256, 1) void vq_mma_kernel() {
    extern __shared__ __align__(128) char smem[];
    const uint32_t sb = smem_u32(smem);
    const int tid  = threadIdx.x;
    const int lane = tid & 31;
    const int wid  = tid >> 5;
    const int wm   = wid & 3;      // warp row group (0..3)
    const int wn   = wid >> 2;     // warp col group (0..1)
    const int n0   = blockIdx.x * 128;

    // ---- load A (z rows) into smem, swizzled ----
    {
        const char* srcA = (const char*)g_zbf16 + (size_t)n0 * 512;
        #pragma unroll
        for (int j = 0; j < 16; j++) {
            int i = tid + j * 256;              // 4096 16B chunks
            int r = i >> 5, c16 = i & 31;
            uint32_t kb = c16 * 16;
            cp_async16(sb + SM_A + r * 512 + (kb ^ ((r & 7) << 4)),
                       srcA + (size_t)r * 512 + kb);
        }
    }
    // ---- load B tile 0 + norms ----
    {
        const char* srcB = (const char*)g_cbbf16;
        #pragma unroll
        for (int j = 0; j < 16; j++) {
            int i = tid + j * 256;
            int r = i >> 5, c16 = i & 31;
            uint32_t kb = c16 * 16;
            cp_async16(sb + SM_B + r * 512 + (kb ^ ((r & 7) << 4)),
                       srcB + (size_t)r * 512 + kb);
        }
        if (tid < 32)
            cp_async16(sb + SM_NK + tid * 16, (const char*)g_cbnorm + tid * 16);
    }
    CP_COMMIT();

    // per-thread z norms for its 4 rows
    float znr[2][2];
    #pragma unroll
    for (int mt = 0; mt < 2; mt++)
        #pragma unroll
        for (int g = 0; g < 2; g++)
            znr[mt][g] = g_znorm[n0 + wm * 32 + mt * 16 + g * 8 + (lane >> 2)];

    // ldmatrix lane addressing (same scheme for A and B)
    const int lrow8 = ((lane >> 3) & 1) * 8 + (lane & 7);
    const uint32_t kext = (lane >> 4) * 16;
    const uint32_t xorv = (uint32_t)(lane & 7) << 4;
    uint32_t aBase[2];
    #pragma unroll
    for (int mt = 0; mt < 2; mt++)
        aBase[mt] = sb + SM_A + (wm * 32 + mt * 16 + lrow8) * 512;
    uint32_t bOff[4];
    #pragma unroll
    for (int np = 0; np < 4; np++)
        bOff[np] = (wn * 64 + np * 16 + lrow8) * 512;

    // candidate lists: [mt*2+g][4]
    float cs[4][4];
    int   ci[4][4];
    #pragma unroll
    for (int l = 0; l < 4; l++)
        #pragma unroll
        for (int j = 0; j < 4; j++) { cs[l][j] = 3.4e38f; ci[l][j] = 0; }

    for (int t = 0; t < NTILES; t++) {
        const int buf = t & 1;
        // prefetch next B tile into the other buffer
        if (t + 1 < NTILES) {
            const char* srcB = (const char*)g_cbbf16 + (size_t)(t + 1) * 128 * 512;
            uint32_t dst = sb + SM_B + (buf ^ 1) * 65536;
            #pragma unroll
            for (int j = 0; j < 16; j++) {
                int i = tid + j * 256;
                int r = i >> 5, c16 = i & 31;
                uint32_t kb = c16 * 16;
                cp_async16(dst + r * 512 + (kb ^ ((r & 7) << 4)),
                           srcB + (size_t)r * 512 + kb);
            }
            if (tid < 32)
                cp_async16(sb + SM_NK + (buf ^ 1) * 512 + tid * 16,
                           (const char*)(g_cbnorm + (t + 1) * 128) + tid * 16);
            CP_COMMIT();
            CP_WAIT1();
        } else {
            CP_WAIT0();
        }
        __syncthreads();

        // ---- 16 k-steps of mma over D=256 ----
        float acc[2][8][4];
        #pragma unroll
        for (int mt = 0; mt < 2; mt++)
            #pragma unroll
            for (int nt = 0; nt < 8; nt++)
                #pragma unroll
                for (int q = 0; q < 4; q++) acc[mt][nt][q] = 0.f;

        const uint32_t bBase = sb + SM_B + buf * 65536;
        #pragma unroll
        for (int ks = 0; ks < 16; ks++) {
            const uint32_t kb = ks * 32;
            uint32_t a[2][4];
            #pragma unroll
            for (int mt = 0; mt < 2; mt++)
                LDSM4(a[mt][0], a[mt][1], a[mt][2], a[mt][3],
                      aBase[mt] + ((kb + kext) ^ xorv));
            uint32_t b[4][4];
            #pragma unroll
            for (int np = 0; np < 4; np++)
                LDSM4(b[np][0], b[np][1], b[np][2], b[np][3],
                      bBase + bOff[np] + ((kb + kext) ^ xorv));
            #pragma unroll
            for (int mt = 0; mt < 2; mt++)
                #pragma unroll
                for (int nt = 0; nt < 8; nt++)
                    MMA16816(acc[mt][nt], a[mt],
                             b[nt >> 1][nt & 1], b[nt >> 1][2 + (nt & 1)]);
        }

        // ---- epilogue: fold norms, update top-4 lists ----
        {
            const float* nk = (const float*)(smem + SM_NK + buf * 512);
            const int cb0 = wn * 64 + 2 * (lane & 3);
            #pragma unroll
            for (int nt = 0; nt < 8; nt++) {
                int c = cb0 + nt * 8;
                float nk0 = nk[c], nk1 = nk[c + 1];
                int kc = t * 128 + c;
                #pragma unroll
                for (int mt = 0; mt < 2; mt++) {
                    float s;
                    s = fmaf(-2.f, acc[mt][nt][0], znr[mt][0] + nk0);
                    INSERT4(mt * 2 + 0, s, kc);
                    s = fmaf(-2.f, acc[mt][nt][1], znr[mt][0] + nk1);
                    INSERT4(mt * 2 + 0, s, kc + 1);
                    s = fmaf(-2.f, acc[mt][nt][2], znr[mt][1] + nk0);
                    INSERT4(mt * 2 + 1, s, kc);
                    s = fmaf(-2.f, acc[mt][nt][3], znr[mt][1] + nk1);
                    INSERT4(mt * 2 + 1, s, kc + 1);
                }
            }
        }
        __syncthreads();   // lists done; safe to overwrite buf next iter
    }

    // ---- write candidates: per row 8 domains x 4 ----
    const int dom = wn * 4 + (lane & 3);
    #pragma unroll
    for (int mt = 0; mt < 2; mt++)
        #pragma unroll
        for (int g = 0; g < 2; g++) {
            int n = n0 + wm * 32 + mt * 16 + g * 8 + (lane >> 2);
            #pragma unroll
            for (int j = 0; j < 4; j++)
                g_cand[n * 32 + dom * 4 + j] = ci[mt * 2 + g][j];
        }
}

// ============================================================
// exact rescore, warp-cooperative (launch #5).
// Block = 8 vectors (one per warp). z staged coalesced into smem.
// Per candidate: warp loads the 1KB codebook row coalesced,
// 8-term fmaf partials, shfl tree reduce, then the reference's
// quantized comparison q = fl(fl(zn+ek) - fl(2*dot)) with
// lowest-index tie-break.
// ============================================================
__global__ __launch_bounds__(256, 4)
void rescore_kernel(const float* __restrict__ z, const float* __restrict__ cb,
                    float* __restrict__ out_idx) {
    __shared__ float zs[8][260];
    const int tid = threadIdx.x, w = tid >> 5, lane = tid & 31;
    const int n0 = blockIdx.x * 8;
    const int b = n0 >> 10, hw0 = n0 & 1023;   // 8 | 1024: same b for block
    const float* zb = z + (size_t)b * (D_ * HW_) + hw0;
    // coalesced transpose staging: 2048 floats, 4 lines per warp-instr
    #pragma unroll
    for (int i = tid; i < 2048; i += 256) {
        int c = i >> 3, ho = i & 7;
        zs[ho][c] = zb[(size_t)c * HW_ + ho];
    }
    __syncthreads();

    const int n = n0 + w;
    const float zn = g_znorm[n];
    // lane-resident z slices: d in [4*lane,4*lane+4) and [128+4*lane, ...)
    float za[4], zc[4];
    #pragma unroll
    for (int j = 0; j < 4; j++) {
        za[j] = zs[w][4 * lane + j];
        zc[j] = zs[w][128 + 4 * lane + j];
    }
    const int kmy = g_cand[n * 32 + lane];

    float q = 3.4e38f;
    int   ki = 0x7fffffff;
    for (int j = 0; j < 32; j++) {
        int k = __shfl_sync(0xffffffffu, kmy, j);
        const float4* cr = (const float4*)(cb + (size_t)k * D_);
        float4 c0 = cr[lane];        // d [4*lane, 4*lane+4)
        float4 c1 = cr[32 + lane];   // d [128+4*lane, ...)
        float p;
        p = za[0] * c0.x;
        p = fmaf(za[1], c0.y, p);
        p = fmaf(za[2], c0.z, p);
        p = fmaf(za[3], c0.w, p);
        p = fmaf(zc[0], c1.x, p);
        p = fmaf(zc[1], c1.y, p);
        p = fmaf(zc[2], c1.z, p);
        p = fmaf(zc[3], c1.w, p);
        #pragma unroll
        for (int off = 16; off > 0; off >>= 1)
            p += __shfl_xor_sync(0xffffffffu, p, off);
        float r = __fadd_rn(zn, g_cbnorm[k]);   // fl(zn + ek)
        float s = fmaf(-2.f, p, r);             // fl(r - 2*dot)
        if (s < q || (s == q && k < ki)) { q = s; ki = k; }
    }
    if (lane == 0) {
        g_idx[n] = ki;
        out_idx[n] = (float)ki;
    }
}

// ============================================================
// gather z_q with exact STE emulation fl(zp + fl(q - zp)) +
// per-block partial sums of (q - zp)^2   (launch #6)
// ============================================================
__global__ void gather_loss(const float* __restrict__ z,
                            const float* __restrict__ cb,
                            float* __restrict__ out_zq) {
    __shared__ float red[256];
    int i = blockIdx.x * 256 + threadIdx.x;
    int hw = i & 1023;
    int c  = (i >> 10) & 255;
    int b  = i >> 18;
    int n  = (b << 10) + hw;
    int k  = g_idx[n];
    float q  = cb[(size_t)k * D_ + c];
    float zv = z[i];
    // straight-through estimator, reproducing the reference's rounding
    out_zq[i] = __fadd_rn(zv, __fsub_rn(q, zv));
    float d = q - zv;
    red[threadIdx.x] = d * d;
    __syncthreads();
    #pragma unroll
    for (int off = 128; off > 0; off >>= 1) {
        if (threadIdx.x < off) red[threadIdx.x] += red[threadIdx.x + off];
        __syncthreads();
    }
    if (threadIdx.x == 0) g_partial[blockIdx.x] = red[0];
}

__global__ void finalize_loss(float* __restrict__ out_loss) {
    __shared__ double red[1024];
    double s = 0.0;
    for (int i = threadIdx.x; i < ZQ_ELEMS / 256; i += 1024)
        s += (double)g_partial[i];
    red[threadIdx.x] = s;
    __syncthreads();
    #pragma unroll
    for (int off = 512; off > 0; off >>= 1) {
        if (threadIdx.x < off) red[threadIdx.x] += red[threadIdx.x + off];
        __syncthreads();
    }
    if (threadIdx.x == 0)
        out_loss[0] = (float)(1.25 * red[0] / (double)ZQ_ELEMS);
}

// ============================================================
extern "C" void kernel_launch(void* const* d_in, const int* in_sizes, int n_in,
                              void* d_out, int out_size) {
    const float* z  = (const float*)d_in[0];
    const float* cb = (const float*)d_in[1];
    float* out      = (float*)d_out;

    float* out_zq   = out;
    float* out_loss = out + ZQ_ELEMS;
    float* out_idx  = out + ZQ_ELEMS + 1;

    cudaFuncSetAttribute(vq_mma_kernel,
                         cudaFuncAttributeMaxDynamicSharedMemorySize, SM_TOTAL);

    znorm_kernel<<<N_TOT / 256, 256>>>(z);                      // #1
    cb_prep_kernel<<<K_TOT / 8, 256>>>(cb);                     // #2
    cvt_z_kernel<<<dim3(D_ / 32, HW_ / 32, 16), dim3(32, 8)>>>(z); // #3

    vq_mma_kernel<<<N_TOT / 128, 256, SM_TOTAL>>>();            // #4 (profiled)

    rescore_kernel<<<N_TOT / 8, 256>>>(z, cb, out_idx);         // #5

    gather_loss<<<ZQ_ELEMS / 256, 256>>>(z, cb, out_zq);        // #6

    finalize_loss<<<1, 1024>>>(out_loss);                       // #7
}

// round 6
// speedup vs baseline: 3.6013x; 1.2052x over previous
#include <cuda_runtime.h>
#include <cuda_bf16.h>
#include <cstdint>

// Problem constants
#define D_    256
#define HW_   1024            // 32*32
#define N_TOT 16384           // 16 * 1024 vectors
#define K_TOT 8192            // codebook entries
#define ZQ_ELEMS 4194304      // 16*256*32*32
#define NTILES 64             // K_TOT / 128 codes per tile
#define SLACK  4e-4f          // compaction threshold above approx min
#define MAXC   16             // max candidates per vector after compaction

// ---- device scratch (no allocations allowed) ----
__device__ float g_cbnorm[K_TOT];
__device__ float g_znorm[N_TOT];
__device__ int   g_idx[N_TOT];
__device__ float g_partial[ZQ_ELEMS / 256];
__device__ __nv_bfloat16 g_zbf16[N_TOT * D_];    // [n][d] row-major (512B rows)
__device__ __nv_bfloat16 g_cbbf16[K_TOT * D_];   // [k][d] row-major (512B rows)
__device__ int   g_cand[N_TOT * MAXC];           // compacted candidates
__device__ int   g_candcnt[N_TOT];               // candidate counts

// ---- smem layout for the MMA kernel (dynamic) ----
#define SM_A   0               // 128 rows x 512B (z tile, resident); reused as
                               // the 64KB candidate table after the K loop
#define SM_B   65536           // 2 x 128 rows x 512B (codebook, dbl buf)
#define SM_NK  196608          // 2 x 128 floats (code norms, dbl buf)
#define SM_TOTAL 197632

// ---- PTX helpers (non-'a' target instructions only) ----
__device__ __forceinline__ uint32_t smem_u32(const void* p) {
    uint32_t a;
    asm("{ .reg .u64 t; cvta.to.shared.u64 t, %1; cvt.u32.u64 %0, t; }"
        : "=r"(a) : "l"(p));
    return a;
}
__device__ __forceinline__ void cp_async16(uint32_t dst, const void* src) {
    asm volatile("cp.async.cg.shared.global [%0], [%1], 16;"
                 :: "r"(dst), "l"(src) : "memory");
}
#define CP_COMMIT() asm volatile("cp.async.commit_group;" ::: "memory")
#define CP_WAIT1()  asm volatile("cp.async.wait_group 1;" ::: "memory")
#define CP_WAIT0()  asm volatile("cp.async.wait_group 0;" ::: "memory")

#define LDSM4(r0, r1, r2, r3, addr)                                        \
    asm volatile("ldmatrix.sync.aligned.m8n8.x4.shared.b16 "               \
                 "{%0,%1,%2,%3}, [%4];"                                    \
                 : "=r"(r0), "=r"(r1), "=r"(r2), "=r"(r3) : "r"(addr))

#define MMA16816(d, a, b0, b1)                                             \
    asm volatile("mma.sync.aligned.m16n8k16.row.col.f32.bf16.bf16.f32 "    \
                 "{%0,%1,%2,%3}, {%4,%5,%6,%7}, {%8,%9}, {%0,%1,%2,%3};"   \
                 : "+f"((d)[0]), "+f"((d)[1]), "+f"((d)[2]), "+f"((d)[3])  \
                 : "r"((a)[0]), "r"((a)[1]), "r"((a)[2]), "r"((a)[3]),     \
                   "r"(b0), "r"(b1))

// sorted-insert into a length-4 ascending list (compile-time L)
#define INSERT4(L, sval, kval) do {                                        \
    if ((sval) < cs[L][3]) {                                               \
        float _vs = (sval); int _vi = (kval);                              \
        _Pragma("unroll")                                                  \
        for (int _j = 0; _j < 4; _j++) {                                   \
            if (_vs < cs[L][_j]) {                                         \
                float _tf = cs[L][_j]; int _ti = ci[L][_j];                \
                cs[L][_j] = _vs; ci[L][_j] = _vi; _vs = _tf; _vi = _ti;    \
            }                                                              \
        }                                                                  \
    }                                                                      \
} while (0)

// ============================================================
// prep: z squared norms per vector (launch #1)
// ============================================================
__global__ void znorm_kernel(const float* __restrict__ z) {
    int n = blockIdx.x * 256 + threadIdx.x;
    int b  = n >> 10;
    int hw = n & 1023;
    const float* p = z + (size_t)b * (D_ * HW_) + hw;
    double s = 0.0;
    #pragma unroll 8
    for (int c = 0; c < D_; c++) {
        float v = p[(size_t)c * HW_];
        s += (double)v * v;
    }
    g_znorm[n] = (float)s;
}

// ============================================================
// prep: fused codebook norms (fp64) + fp32->bf16 convert (launch #2)
// ============================================================
__global__ void cb_prep_kernel(const float* __restrict__ cb) {
    int warp = threadIdx.x >> 5;
    int lane = threadIdx.x & 31;
    int k = blockIdx.x * 8 + warp;
    const float4* row = (const float4*)(cb + (size_t)k * D_);
    float4 v0 = row[lane * 2];
    float4 v1 = row[lane * 2 + 1];
    double s = (double)v0.x * v0.x + (double)v0.y * v0.y
             + (double)v0.z * v0.z + (double)v0.w * v0.w
             + (double)v1.x * v1.x + (double)v1.y * v1.y
             + (double)v1.z * v1.z + (double)v1.w * v1.w;
    #pragma unroll
    for (int off = 16; off > 0; off >>= 1)
        s += __shfl_xor_sync(0xffffffffu, s, off);
    if (lane == 0) g_cbnorm[k] = (float)s;
    __nv_bfloat162 a = __floats2bfloat162_rn(v0.x, v0.y);
    __nv_bfloat162 b = __floats2bfloat162_rn(v0.z, v0.w);
    __nv_bfloat162 c = __floats2bfloat162_rn(v1.x, v1.y);
    __nv_bfloat162 d = __floats2bfloat162_rn(v1.z, v1.w);
    uint4 o;
    o.x = *(const uint32_t*)&a; o.y = *(const uint32_t*)&b;
    o.z = *(const uint32_t*)&c; o.w = *(const uint32_t*)&d;
    *(uint4*)(g_cbbf16 + (size_t)k * D_ + lane * 8) = o;
}

// ============================================================
// prep: z [b,c,hw] fp32 -> g_zbf16 [n][c] bf16 (transpose) (launch #3)
// ============================================================
__global__ void cvt_z_kernel(const float* __restrict__ z) {
    __shared__ float t[32][33];
    int b  = blockIdx.z;
    int hw0 = blockIdx.y * 32;
    int c0  = blockIdx.x * 32;
    int tx = threadIdx.x, ty = threadIdx.y;   // 32 x 8
    #pragma unroll
    for (int r = 0; r < 4; r++) {
        int c = c0 + ty + r * 8;
        t[ty + r * 8][tx] = z[((size_t)b * D_ + c) * HW_ + hw0 + tx];
    }
    __syncthreads();
    #pragma unroll
    for (int r = 0; r < 4; r++) {
        int n = b * HW_ + hw0 + ty + r * 8;
        g_zbf16[(size_t)n * D_ + c0 + tx] = __float2bfloat16_rn(t[tx][ty + r * 8]);
    }
}

// ============================================================
// main: bf16 mma.sync candidate GEMM (launch #4 -> ncu profiles this).
// grid = 128 CTAs (128 z-rows each), 512 threads (16 warps, 4m x 4n).
// Warp tile 32(m) x 32(n); per thread 2 m16 x 4 n8 tiles, 32 accums.
// Scores tracked WITHOUT zn (row-constant; ordering invariant).
// Per-thread per-row top-4 lists over 16 domains/row, then
// threshold compaction (min + SLACK) to <= MAXC candidates/row.
// ============================================================
__global__ __launch_bounds__(512, 1) void vq_mma_kernel() {
    extern __shared__ __align__(128) char smem[];
    const uint32_t sb = smem_u32(smem);
    const int tid  = threadIdx.x;
    const int lane = tid & 31;
    const int wid  = tid >> 5;
    const int wm   = wid & 3;      // warp row group (0..3), 32 rows each
    const int wn   = wid >> 2;     // warp col group (0..3), 32 cols each
    const int n0   = blockIdx.x * 128;

    // ---- load A (z rows) into smem, swizzled: 4096 chunks, 8/thread ----
    {
        const char* srcA = (const char*)g_zbf16 + (size_t)n0 * 512;
        #pragma unroll
        for (int j = 0; j < 8; j++) {
            int i = tid + j * 512;
            int r = i >> 5, c16 = i & 31;
            uint32_t kb = c16 * 16;
            cp_async16(sb + SM_A + r * 512 + (kb ^ ((r & 7) << 4)),
                       srcA + (size_t)r * 512 + kb);
        }
    }
    // ---- load B tile 0 + norms ----
    {
        const char* srcB = (const char*)g_cbbf16;
        #pragma unroll
        for (int j = 0; j < 8; j++) {
            int i = tid + j * 512;
            int r = i >> 5, c16 = i & 31;
            uint32_t kb = c16 * 16;
            cp_async16(sb + SM_B + r * 512 + (kb ^ ((r & 7) << 4)),
                       srcB + (size_t)r * 512 + kb);
        }
        if (tid < 32)
            cp_async16(sb + SM_NK + tid * 16, (const char*)g_cbnorm + tid * 16);
    }
    CP_COMMIT();

    // ldmatrix lane addressing
    const int lrow8 = ((lane >> 3) & 1) * 8 + (lane & 7);
    const uint32_t kext = (lane >> 4) * 16;
    const uint32_t xorv = (uint32_t)(lane & 7) << 4;
    uint32_t aBase[2];
    #pragma unroll
    for (int mt = 0; mt < 2; mt++)
        aBase[mt] = sb + SM_A + (wm * 32 + mt * 16 + lrow8) * 512;
    uint32_t bOff[2];
    #pragma unroll
    for (int np = 0; np < 2; np++)
        bOff[np] = (wn * 32 + np * 16 + lrow8) * 512;

    // candidate lists: [mt*2+g][4], scores exclude zn
    float cs[4][4];
    int   ci[4][4];
    #pragma unroll
    for (int l = 0; l < 4; l++)
        #pragma unroll
        for (int j = 0; j < 4; j++) { cs[l][j] = 3.4e38f; ci[l][j] = 0; }

    for (int t = 0; t < NTILES; t++) {
        const int buf = t & 1;
        if (t + 1 < NTILES) {
            const char* srcB = (const char*)g_cbbf16 + (size_t)(t + 1) * 128 * 512;
            uint32_t dst = sb + SM_B + (buf ^ 1) * 65536;
            #pragma unroll
            for (int j = 0; j < 8; j++) {
                int i = tid + j * 512;
                int r = i >> 5, c16 = i & 31;
                uint32_t kb = c16 * 16;
                cp_async16(dst + r * 512 + (kb ^ ((r & 7) << 4)),
                           srcB + (size_t)r * 512 + kb);
            }
            if (tid < 32)
                cp_async16(sb + SM_NK + (buf ^ 1) * 512 + tid * 16,
                           (const char*)(g_cbnorm + (t + 1) * 128) + tid * 16);
            CP_COMMIT();
            CP_WAIT1();
        } else {
            CP_WAIT0();
        }
        __syncthreads();

        // ---- 16 k-steps of mma over D=256 ----
        float acc[2][4][4];
        #pragma unroll
        for (int mt = 0; mt < 2; mt++)
            #pragma unroll
            for (int nt = 0; nt < 4; nt++)
                #pragma unroll
                for (int q = 0; q < 4; q++) acc[mt][nt][q] = 0.f;

        const uint32_t bBase = sb + SM_B + buf * 65536;
        #pragma unroll
        for (int ks = 0; ks < 16; ks++) {
            const uint32_t kb = ks * 32;
            uint32_t a[2][4];
            #pragma unroll
            for (int mt = 0; mt < 2; mt++)
                LDSM4(a[mt][0], a[mt][1], a[mt][2], a[mt][3],
                      aBase[mt] + ((kb + kext) ^ xorv));
            uint32_t b[2][4];
            #pragma unroll
            for (int np = 0; np < 2; np++)
                LDSM4(b[np][0], b[np][1], b[np][2], b[np][3],
                      bBase + bOff[np] + ((kb + kext) ^ xorv));
            #pragma unroll
            for (int mt = 0; mt < 2; mt++)
                #pragma unroll
                for (int nt = 0; nt < 4; nt++)
                    MMA16816(acc[mt][nt], a[mt],
                             b[nt >> 1][nt & 1], b[nt >> 1][2 + (nt & 1)]);
        }

        // ---- epilogue: s = nk - 2*dot (zn dropped), update top-4 ----
        {
            const float* nk = (const float*)(smem + SM_NK + buf * 512);
            const int cb0 = wn * 32 + 2 * (lane & 3);
            #pragma unroll
            for (int nt = 0; nt < 4; nt++) {
                int c = cb0 + nt * 8;
                float nk0 = nk[c], nk1 = nk[c + 1];
                int kc = t * 128 + c;
                #pragma unroll
                for (int mt = 0; mt < 2; mt++) {
                    float s;
                    s = fmaf(-2.f, acc[mt][nt][0], nk0);
                    INSERT4(mt * 2 + 0, s, kc);
                    s = fmaf(-2.f, acc[mt][nt][1], nk1);
                    INSERT4(mt * 2 + 0, s, kc + 1);
                    s = fmaf(-2.f, acc[mt][nt][2], nk0);
                    INSERT4(mt * 2 + 1, s, kc);
                    s = fmaf(-2.f, acc[mt][nt][3], nk1);
                    INSERT4(mt * 2 + 1, s, kc + 1);
                }
            }
        }
        __syncthreads();   // lists done; safe to overwrite buf next iter
    }

    // ---- dump lists to smem table (reuse A region): row x 16dom x 4 ----
    {
        float* tabS = (float*)smem;          // [128][64]
        int*   tabI = (int*)(smem + 32768);  // [128][64]
        const int dom = wn * 4 + (lane & 3);
        #pragma unroll
        for (int mt = 0; mt < 2; mt++)
            #pragma unroll
            for (int g = 0; g < 2; g++) {
                int r = wm * 32 + mt * 16 + g * 8 + (lane >> 2);
                #pragma unroll
                for (int j = 0; j < 4; j++) {
                    tabS[r * 64 + dom * 4 + j] = cs[mt * 2 + g][j];
                    tabI[r * 64 + dom * 4 + j] = ci[mt * 2 + g][j];
                }
            }
    }
    __syncthreads();

    // ---- threshold compaction: one thread per row ----
    if (tid < 128) {
        const float* tabS = (const float*)smem;
        const int*   tabI = (const int*)(smem + 32768);
        const float* es = tabS + tid * 64;
        const int*   ei = tabI + tid * 64;
        float mn = es[0];
        #pragma unroll 8
        for (int i = 1; i < 64; i++) mn = fminf(mn, es[i]);
        float thr = mn + SLACK;
        int cnt = 0;
        int n = n0 + tid;
        #pragma unroll 8
        for (int i = 0; i < 64; i++) {
            if (es[i] <= thr && cnt < MAXC)
                g_cand[n * MAXC + cnt++] = ei[i];
        }
        g_candcnt[n] = cnt;
    }
}

// ============================================================
// exact rescore, warp-cooperative over the compacted candidate
// set (typically 2-3). Reference-quantized comparison:
// q = fl(fl(zn+ek) - fl(2*dot)), lowest-index tie-break.
// ============================================================
__global__ __launch_bounds__(256, 4)
void rescore_kernel(const float* __restrict__ z, const float* __restrict__ cb,
                    float* __restrict__ out_idx) {
    __shared__ float zs[8][260];
    const int tid = threadIdx.x, w = tid >> 5, lane = tid & 31;
    const int n0 = blockIdx.x * 8;
    const int b = n0 >> 10, hw0 = n0 & 1023;   // 8 | 1024: same b for block
    const float* zb = z + (size_t)b * (D_ * HW_) + hw0;
    #pragma unroll
    for (int i = tid; i < 2048; i += 256) {
        int c = i >> 3, ho = i & 7;
        zs[ho][c] = zb[(size_t)c * HW_ + ho];
    }
    __syncthreads();

    const int n = n0 + w;
    const float zn = g_znorm[n];
    float za[4], zc[4];
    #pragma unroll
    for (int j = 0; j < 4; j++) {
        za[j] = zs[w][4 * lane + j];
        zc[j] = zs[w][128 + 4 * lane + j];
    }
    const int cnt = g_candcnt[n];

    float q = 3.4e38f;
    int   ki = 0x7fffffff;
    for (int j = 0; j < cnt; j++) {
        int k = g_cand[n * MAXC + j];
        const float4* cr = (const float4*)(cb + (size_t)k * D_);
        float4 c0 = cr[lane];
        float4 c1 = cr[32 + lane];
        float p;
        p = za[0] * c0.x;
        p = fmaf(za[1], c0.y, p);
        p = fmaf(za[2], c0.z, p);
        p = fmaf(za[3], c0.w, p);
        p = fmaf(zc[0], c1.x, p);
        p = fmaf(zc[1], c1.y, p);
        p = fmaf(zc[2], c1.z, p);
        p = fmaf(zc[3], c1.w, p);
        #pragma unroll
        for (int off = 16; off > 0; off >>= 1)
            p += __shfl_xor_sync(0xffffffffu, p, off);
        float r = __fadd_rn(zn, g_cbnorm[k]);   // fl(zn + ek)
        float s = fmaf(-2.f, p, r);             // fl(r - 2*dot)
        if (s < q || (s == q && k < ki)) { q = s; ki = k; }
    }
    if (lane == 0) {
        g_idx[n] = ki;
        out_idx[n] = (float)ki;
    }
}

// ============================================================
// gather z_q with exact STE emulation fl(zp + fl(q - zp)) +
// per-block partial sums of (q - zp)^2
// ============================================================
__global__ void gather_loss(const float* __restrict__ z,
                            const float* __restrict__ cb,
                            float* __restrict__ out_zq) {
    __shared__ float red[256];
    int i = blockIdx.x * 256 + threadIdx.x;
    int hw = i & 1023;
    int c  = (i >> 10) & 255;
    int b  = i >> 18;
    int n  = (b << 10) + hw;
    int k  = g_idx[n];
    float q  = cb[(size_t)k * D_ + c];
    float zv = z[i];
    out_zq[i] = __fadd_rn(zv, __fsub_rn(q, zv));
    float d = q - zv;
    red[threadIdx.x] = d * d;
    __syncthreads();
    #pragma unroll
    for (int off = 128; off > 0; off >>= 1) {
        if (threadIdx.x < off) red[threadIdx.x] += red[threadIdx.x + off];
        __syncthreads();
    }
    if (threadIdx.x == 0) g_partial[blockIdx.x] = red[0];
}

__global__ void finalize_loss(float* __restrict__ out_loss) {
    __shared__ double red[1024];
    double s = 0.0;
    for (int i = threadIdx.x; i < ZQ_ELEMS / 256; i += 1024)
        s += (double)g_partial[i];
    red[threadIdx.x] = s;
    __syncthreads();
    #pragma unroll
    for (int off = 512; off > 0; off >>= 1) {
        if (threadIdx.x < off) red[threadIdx.x] += red[threadIdx.x + off];
        __syncthreads();
    }
    if (threadIdx.x == 0)
        out_loss[0] = (float)(1.25 * red[0] / (double)ZQ_ELEMS);
}

// ============================================================
extern "C" void kernel_launch(void* const* d_in, const int* in_sizes, int n_in,
                              void* d_out, int out_size) {
    const float* z  = (const float*)d_in[0];
    const float* cb = (const float*)d_in[1];
    float* out      = (float*)d_out;

    float* out_zq   = out;
    float* out_loss = out + ZQ_ELEMS;
    float* out_idx  = out + ZQ_ELEMS + 1;

    cudaFuncSetAttribute(vq_mma_kernel,
                         cudaFuncAttributeMaxDynamicSharedMemorySize, SM_TOTAL);

    znorm_kernel<<<N_TOT / 256, 256>>>(z);                      // #1
    cb_prep_kernel<<<K_TOT / 8, 256>>>(cb);                     // #2
    cvt_z_kernel<<<dim3(D_ / 32, HW_ / 32, 16), dim3(32, 8)>>>(z); // #3

    vq_mma_kernel<<<N_TOT / 128, 512, SM_TOTAL>>>();            // #4 (profiled)

    rescore_kernel<<<N_TOT / 8, 256>>>(z, cb, out_idx);         // #5

    gather_loss<<<ZQ_ELEMS / 256, 256>>>(z, cb, out_zq);        // #6

    finalize_loss<<<1, 1024>>>(out_loss);                       // #7
}

// round 7
// speedup vs baseline: 4.2546x; 1.1814x over previous
#include <cuda_runtime.h>
#include <cuda_bf16.h>
#include <cstdint>

// Problem constants
#define D_    256
#define HW_   1024            // 32*32
#define N_TOT 16384           // 16 * 1024 vectors
#define K_TOT 8192            // codebook entries
#define ZQ_ELEMS 4194304      // 16*256*32*32
#define NTILES 64             // K_TOT / 128 codes per tile
#define SLACK  4e-4f          // compaction threshold above approx min
#define MAXC   16             // max candidates per vector after compaction

// ---- device scratch (no allocations allowed) ----
__device__ float g_cbnorm[K_TOT];
__device__ float g_znorm[N_TOT];
__device__ int   g_idx[N_TOT];
__device__ float g_partial[ZQ_ELEMS / 256];
__device__ __nv_bfloat16 g_zbf16[N_TOT * D_];    // [n][d] row-major (512B rows)
__device__ __nv_bfloat16 g_cbbf16[K_TOT * D_];   // [k][d] row-major (512B rows)
__device__ int   g_cand[N_TOT * MAXC];           // compacted candidates
__device__ int   g_candcnt[N_TOT];               // candidate counts

// ---- smem layout for the MMA kernel (dynamic) ----
#define SM_A   0               // 128 rows x 512B (z tile, resident); reused as
                               // the candidate table after the K loop
#define SM_B   65536           // 2 x 128 rows x 512B (codebook, dbl buf)
#define SM_NK  196608          // 2 x 128 floats (code norms, dbl buf)
#define SM_TOTAL 197632

// ---- PTX helpers (non-'a' target instructions only) ----
__device__ __forceinline__ uint32_t smem_u32(const void* p) {
    uint32_t a;
    asm("{ .reg .u64 t; cvta.to.shared.u64 t, %1; cvt.u32.u64 %0, t; }"
        : "=r"(a) : "l"(p));
    return a;
}
__device__ __forceinline__ void cp_async16(uint32_t dst, const void* src) {
    asm volatile("cp.async.cg.shared.global [%0], [%1], 16;"
                 :: "r"(dst), "l"(src) : "memory");
}
#define CP_COMMIT() asm volatile("cp.async.commit_group;" ::: "memory")
#define CP_WAIT1()  asm volatile("cp.async.wait_group 1;" ::: "memory")
#define CP_WAIT0()  asm volatile("cp.async.wait_group 0;" ::: "memory")

#define LDSM4(r0, r1, r2, r3, addr)                                        \
    asm volatile("ldmatrix.sync.aligned.m8n8.x4.shared.b16 "               \
                 "{%0,%1,%2,%3}, [%4];"                                    \
                 : "=r"(r0), "=r"(r1), "=r"(r2), "=r"(r3) : "r"(addr))

#define MMA16816(d, a, b0, b1)                                             \
    asm volatile("mma.sync.aligned.m16n8k16.row.col.f32.bf16.bf16.f32 "    \
                 "{%0,%1,%2,%3}, {%4,%5,%6,%7}, {%8,%9}, {%0,%1,%2,%3};"   \
                 : "+f"((d)[0]), "+f"((d)[1]), "+f"((d)[2]), "+f"((d)[3])  \
                 : "r"((a)[0]), "r"((a)[1]), "r"((a)[2]), "r"((a)[3]),     \
                   "r"(b0), "r"(b1))

// branchless top-3 min-chain update with a packed (score|local) u32
#define UPD3(CH, pval, loc) do {                                           \
    uint32_t _u = (__float_as_uint(pval) & 0xFFFFFF00u) | (loc);           \
    uint32_t _t1 = max(_u, (CH)[0]); (CH)[0] = min(_u, (CH)[0]);           \
    uint32_t _t2 = max(_t1, (CH)[1]); (CH)[1] = min(_t1, (CH)[1]);         \
    (CH)[2] = min(_t2, (CH)[2]);                                           \
} while (0)

// ============================================================
// prep: z squared norms per vector (launch #1)
// ============================================================
__global__ void znorm_kernel(const float* __restrict__ z) {
    int n = blockIdx.x * 256 + threadIdx.x;
    int b  = n >> 10;
    int hw = n & 1023;
    const float* p = z + (size_t)b * (D_ * HW_) + hw;
    double s = 0.0;
    #pragma unroll 8
    for (int c = 0; c < D_; c++) {
        float v = p[(size_t)c * HW_];
        s += (double)v * v;
    }
    g_znorm[n] = (float)s;
}

// ============================================================
// prep: fused codebook norms (fp64) + fp32->bf16 convert (launch #2)
// ============================================================
__global__ void cb_prep_kernel(const float* __restrict__ cb) {
    int warp = threadIdx.x >> 5;
    int lane = threadIdx.x & 31;
    int k = blockIdx.x * 8 + warp;
    const float4* row = (const float4*)(cb + (size_t)k * D_);
    float4 v0 = row[lane * 2];
    float4 v1 = row[lane * 2 + 1];
    double s = (double)v0.x * v0.x + (double)v0.y * v0.y
             + (double)v0.z * v0.z + (double)v0.w * v0.w
             + (double)v1.x * v1.x + (double)v1.y * v1.y
             + (double)v1.z * v1.z + (double)v1.w * v1.w;
    #pragma unroll
    for (int off = 16; off > 0; off >>= 1)
        s += __shfl_xor_sync(0xffffffffu, s, off);
    if (lane == 0) g_cbnorm[k] = (float)s;
    __nv_bfloat162 a = __floats2bfloat162_rn(v0.x, v0.y);
    __nv_bfloat162 b = __floats2bfloat162_rn(v0.z, v0.w);
    __nv_bfloat162 c = __floats2bfloat162_rn(v1.x, v1.y);
    __nv_bfloat162 d = __floats2bfloat162_rn(v1.z, v1.w);
    uint4 o;
    o.x = *(const uint32_t*)&a; o.y = *(const uint32_t*)&b;
    o.z = *(const uint32_t*)&c; o.w = *(const uint32_t*)&d;
    *(uint4*)(g_cbbf16 + (size_t)k * D_ + lane * 8) = o;
}

// ============================================================
// prep: z [b,c,hw] fp32 -> g_zbf16 [n][c] bf16 (transpose) (launch #3)
// ============================================================
__global__ void cvt_z_kernel(const float* __restrict__ z) {
    __shared__ float t[32][33];
    int b  = blockIdx.z;
    int hw0 = blockIdx.y * 32;
    int c0  = blockIdx.x * 32;
    int tx = threadIdx.x, ty = threadIdx.y;   // 32 x 8
    #pragma unroll
    for (int r = 0; r < 4; r++) {
        int c = c0 + ty + r * 8;
        t[ty + r * 8][tx] = z[((size_t)b * D_ + c) * HW_ + hw0 + tx];
    }
    __syncthreads();
    #pragma unroll
    for (int r = 0; r < 4; r++) {
        int n = b * HW_ + hw0 + ty + r * 8;
        g_zbf16[(size_t)n * D_ + c0 + tx] = __float2bfloat16_rn(t[tx][ty + r * 8]);
    }
}

// ============================================================
// main: bf16 mma.sync candidate GEMM (launch #4 -> ncu profiles this).
// grid = 128 CTAs (128 z-rows each), 512 threads (16 warps, 4m x 4n).
// Warp tile 32(m) x 32(n); per thread 2 m16 x 4 n8 tiles, 32 accums.
// Epilogue: branchless packed-min top-3 per domain.
//   p = fma(acc, -32, fl(nk*16+2))  in [1.82, 2.18] (positive -> bit-
//   monotone); low 8 bits replaced by local id (tile*4 + slot).
//   32 domains/row (per thread-column-group x n-half), top-3 each,
//   then threshold compaction (min + SLACK) to <= MAXC candidates/row.
// ============================================================
__global__ __launch_bounds__(512, 1) void vq_mma_kernel() {
    extern __shared__ __align__(128) char smem[];
    const uint32_t sb = smem_u32(smem);
    const int tid  = threadIdx.x;
    const int lane = tid & 31;
    const int wid  = tid >> 5;
    const int wm   = wid & 3;      // warp row group (0..3), 32 rows each
    const int wn   = wid >> 2;     // warp col group (0..3), 32 cols each
    const int n0   = blockIdx.x * 128;

    // ---- load A (z rows) into smem, swizzled: 4096 chunks, 8/thread ----
    {
        const char* srcA = (const char*)g_zbf16 + (size_t)n0 * 512;
        #pragma unroll
        for (int j = 0; j < 8; j++) {
            int i = tid + j * 512;
            int r = i >> 5, c16 = i & 31;
            uint32_t kb = c16 * 16;
            cp_async16(sb + SM_A + r * 512 + (kb ^ ((r & 7) << 4)),
                       srcA + (size_t)r * 512 + kb);
        }
    }
    // ---- load B tile 0 + norms ----
    {
        const char* srcB = (const char*)g_cbbf16;
        #pragma unroll
        for (int j = 0; j < 8; j++) {
            int i = tid + j * 512;
            int r = i >> 5, c16 = i & 31;
            uint32_t kb = c16 * 16;
            cp_async16(sb + SM_B + r * 512 + (kb ^ ((r & 7) << 4)),
                       srcB + (size_t)r * 512 + kb);
        }
        if (tid < 32)
            cp_async16(sb + SM_NK + tid * 16, (const char*)g_cbnorm + tid * 16);
    }
    CP_COMMIT();

    // ldmatrix lane addressing
    const int lrow8 = ((lane >> 3) & 1) * 8 + (lane & 7);
    const uint32_t kext = (lane >> 4) * 16;
    const uint32_t xorv = (uint32_t)(lane & 7) << 4;
    uint32_t aBase[2];
    #pragma unroll
    for (int mt = 0; mt < 2; mt++)
        aBase[mt] = sb + SM_A + (wm * 32 + mt * 16 + lrow8) * 512;
    uint32_t bOff[2];
    #pragma unroll
    for (int np = 0; np < 2; np++)
        bOff[np] = (wn * 32 + np * 16 + lrow8) * 512;

    // packed top-3 chains: [ (mt*2+rowgroup)*2 + half ][3]
    uint32_t ch[8][3];
    #pragma unroll
    for (int l = 0; l < 8; l++)
        #pragma unroll
        for (int j = 0; j < 3; j++) ch[l][j] = 0xFFFFFFFFu;

    for (int t = 0; t < NTILES; t++) {
        const int buf = t & 1;
        if (t + 1 < NTILES) {
            const char* srcB = (const char*)g_cbbf16 + (size_t)(t + 1) * 128 * 512;
            uint32_t dst = sb + SM_B + (buf ^ 1) * 65536;
            #pragma unroll
            for (int j = 0; j < 8; j++) {
                int i = tid + j * 512;
                int r = i >> 5, c16 = i & 31;
                uint32_t kb = c16 * 16;
                cp_async16(dst + r * 512 + (kb ^ ((r & 7) << 4)),
                           srcB + (size_t)r * 512 + kb);
            }
            if (tid < 32)
                cp_async16(sb + SM_NK + (buf ^ 1) * 512 + tid * 16,
                           (const char*)(g_cbnorm + (t + 1) * 128) + tid * 16);
            CP_COMMIT();
            CP_WAIT1();
        } else {
            CP_WAIT0();
        }
        __syncthreads();

        // ---- 16 k-steps of mma over D=256 ----
        float acc[2][4][4];
        #pragma unroll
        for (int mt = 0; mt < 2; mt++)
            #pragma unroll
            for (int nt = 0; nt < 4; nt++)
                #pragma unroll
                for (int q = 0; q < 4; q++) acc[mt][nt][q] = 0.f;

        const uint32_t bBase = sb + SM_B + buf * 65536;
        #pragma unroll
        for (int ks = 0; ks < 16; ks++) {
            const uint32_t kb = ks * 32;
            uint32_t a[2][4];
            #pragma unroll
            for (int mt = 0; mt < 2; mt++)
                LDSM4(a[mt][0], a[mt][1], a[mt][2], a[mt][3],
                      aBase[mt] + ((kb + kext) ^ xorv));
            uint32_t b[2][4];
            #pragma unroll
            for (int np = 0; np < 2; np++)
                LDSM4(b[np][0], b[np][1], b[np][2], b[np][3],
                      bBase + bOff[np] + ((kb + kext) ^ xorv));
            #pragma unroll
            for (int mt = 0; mt < 2; mt++)
                #pragma unroll
                for (int nt = 0; nt < 4; nt++)
                    MMA16816(acc[mt][nt], a[mt],
                             b[nt >> 1][nt & 1], b[nt >> 1][2 + (nt & 1)]);
        }

        // ---- epilogue: packed branchless top-3 updates ----
        {
            const float* nk = (const float*)(smem + SM_NK + buf * 512);
            const int cb0 = wn * 32 + 2 * (lane & 3);
            const uint32_t tb4 = (uint32_t)t * 4;
            #pragma unroll
            for (int nt = 0; nt < 4; nt++) {
                int c = cb0 + nt * 8;
                float nkp0 = fmaf(nk[c],     16.f, 2.f);
                float nkp1 = fmaf(nk[c + 1], 16.f, 2.f);
                const int half = nt >> 1;
                const uint32_t loc0 = tb4 + (uint32_t)(nt & 1) * 2;
                const uint32_t loc1 = loc0 + 1;
                #pragma unroll
                for (int mt = 0; mt < 2; mt++) {
                    UPD3(ch[(mt * 2 + 0) * 2 + half],
                         fmaf(acc[mt][nt][0], -32.f, nkp0), loc0);
                    UPD3(ch[(mt * 2 + 0) * 2 + half],
                         fmaf(acc[mt][nt][1], -32.f, nkp1), loc1);
                    UPD3(ch[(mt * 2 + 1) * 2 + half],
                         fmaf(acc[mt][nt][2], -32.f, nkp0), loc0);
                    UPD3(ch[(mt * 2 + 1) * 2 + half],
                         fmaf(acc[mt][nt][3], -32.f, nkp1), loc1);
                }
            }
        }
        __syncthreads();   // safe to overwrite buf next iter
    }

    // ---- dump decoded (score, k) to smem table: [128 rows][32 dom][3] ----
    {
        uint32_t* tabS = (uint32_t*)smem;            // 48KB
        int*      tabK = (int*)(smem + 49152);       // 48KB
        const int colbase = wn * 32 + 2 * (lane & 3);
        #pragma unroll
        for (int mt = 0; mt < 2; mt++)
            #pragma unroll
            for (int rg = 0; rg < 2; rg++) {
                int r = wm * 32 + mt * 16 + rg * 8 + (lane >> 2);
                #pragma unroll
                for (int half = 0; half < 2; half++) {
                    int dom = wn * 4 + (lane & 3) + half * 16;
                    const uint32_t* c3 = ch[(mt * 2 + rg) * 2 + half];
                    #pragma unroll
                    for (int j = 0; j < 3; j++) {
                        uint32_t e = c3[j];
                        uint32_t loc = e & 255u;
                        int k = (int)(loc >> 2) * 128 + colbase + half * 16
                              + (int)((loc >> 1) & 1) * 8 + (int)(loc & 1);
                        tabS[r * 96 + dom * 3 + j] = e & 0xFFFFFF00u;
                        tabK[r * 96 + dom * 3 + j] = k;
                    }
                }
            }
    }
    __syncthreads();

    // ---- threshold compaction: one thread per row ----
    if (tid < 128) {
        const uint32_t* es = (const uint32_t*)smem + tid * 96;
        const int*      ek = (const int*)(smem + 49152) + tid * 96;
        uint32_t mn = es[0];
        #pragma unroll 8
        for (int i = 1; i < 96; i++) mn = min(mn, es[i]);
        float thr = __uint_as_float(mn) + SLACK * 16.f;   // packed scale
        int cnt = 0;
        int n = n0 + tid;
        #pragma unroll 8
        for (int i = 0; i < 96; i++) {
            if (__uint_as_float(es[i]) <= thr && cnt < MAXC)
                g_cand[n * MAXC + cnt++] = ek[i];
        }
        g_candcnt[n] = cnt;
    }
}

// ============================================================
// exact rescore, warp-cooperative over the compacted candidate
// set (typically 1-3). Reference-quantized comparison:
// q = fl(fl(zn+ek) - fl(2*dot)), lowest-index tie-break.
// ============================================================
__global__ __launch_bounds__(256, 4)
void rescore_kernel(const float* __restrict__ z, const float* __restrict__ cb,
                    float* __restrict__ out_idx) {
    __shared__ float zs[8][260];
    const int tid = threadIdx.x, w = tid >> 5, lane = tid & 31;
    const int n0 = blockIdx.x * 8;
    const int b = n0 >> 10, hw0 = n0 & 1023;   // 8 | 1024: same b for block
    const float* zb = z + (size_t)b * (D_ * HW_) + hw0;
    #pragma unroll
    for (int i = tid; i < 2048; i += 256) {
        int c = i >> 3, ho = i & 7;
        zs[ho][c] = zb[(size_t)c * HW_ + ho];
    }
    __syncthreads();

    const int n = n0 + w;
    const float zn = g_znorm[n];
    float za[4], zc[4];
    #pragma unroll
    for (int j = 0; j < 4; j++) {
        za[j] = zs[w][4 * lane + j];
        zc[j] = zs[w][128 + 4 * lane + j];
    }
    const int cnt = g_candcnt[n];

    float q = 3.4e38f;
    int   ki = 0x7fffffff;
    for (int j = 0; j < cnt; j++) {
        int k = g_cand[n * MAXC + j];
        const float4* cr = (const float4*)(cb + (size_t)k * D_);
        float4 c0 = cr[lane];
        float4 c1 = cr[32 + lane];
        float p;
        p = za[0] * c0.x;
        p = fmaf(za[1], c0.y, p);
        p = fmaf(za[2], c0.z, p);
        p = fmaf(za[3], c0.w, p);
        p = fmaf(zc[0], c1.x, p);
        p = fmaf(zc[1], c1.y, p);
        p = fmaf(zc[2], c1.z, p);
        p = fmaf(zc[3], c1.w, p);
        #pragma unroll
        for (int off = 16; off > 0; off >>= 1)
            p += __shfl_xor_sync(0xffffffffu, p, off);
        float r = __fadd_rn(zn, g_cbnorm[k]);   // fl(zn + ek)
        float s = fmaf(-2.f, p, r);             // fl(r - 2*dot)
        if (s < q || (s == q && k < ki)) { q = s; ki = k; }
    }
    if (lane == 0) {
        g_idx[n] = ki;
        out_idx[n] = (float)ki;
    }
}

// ============================================================
// gather z_q with exact STE emulation fl(zp + fl(q - zp)) +
// per-block partial sums of (q - zp)^2
// ============================================================
__global__ void gather_loss(const float* __restrict__ z,
                            const float* __restrict__ cb,
                            float* __restrict__ out_zq) {
    __shared__ float red[256];
    int i = blockIdx.x * 256 + threadIdx.x;
    int hw = i & 1023;
    int c  = (i >> 10) & 255;
    int b  = i >> 18;
    int n  = (b << 10) + hw;
    int k  = g_idx[n];
    float q  = cb[(size_t)k * D_ + c];
    float zv = z[i];
    out_zq[i] = __fadd_rn(zv, __fsub_rn(q, zv));
    float d = q - zv;
    red[threadIdx.x] = d * d;
    __syncthreads();
    #pragma unroll
    for (int off = 128; off > 0; off >>= 1) {
        if (threadIdx.x < off) red[threadIdx.x] += red[threadIdx.x + off];
        __syncthreads();
    }
    if (threadIdx.x == 0) g_partial[blockIdx.x] = red[0];
}

__global__ void finalize_loss(float* __restrict__ out_loss) {
    __shared__ double red[1024];
    double s = 0.0;
    for (int i = threadIdx.x; i < ZQ_ELEMS / 256; i += 1024)
        s += (double)g_partial[i];
    red[threadIdx.x] = s;
    __syncthreads();
    #pragma unroll
    for (int off = 512; off > 0; off >>= 1) {
        if (threadIdx.x < off) red[threadIdx.x] += red[threadIdx.x + off];
        __syncthreads();
    }
    if (threadIdx.x == 0)
        out_loss[0] = (float)(1.25 * red[0] / (double)ZQ_ELEMS);
}

// ============================================================
extern "C" void kernel_launch(void* const* d_in, const int* in_sizes, int n_in,
                              void* d_out, int out_size) {
    const float* z  = (const float*)d_in[0];
    const float* cb = (const float*)d_in[1];
    float* out      = (float*)d_out;

    float* out_zq   = out;
    float* out_loss = out + ZQ_ELEMS;
    float* out_idx  = out + ZQ_ELEMS + 1;

    cudaFuncSetAttribute(vq_mma_kernel,
                         cudaFuncAttributeMaxDynamicSharedMemorySize, SM_TOTAL);

    znorm_kernel<<<N_TOT / 256, 256>>>(z);                      // #1
    cb_prep_kernel<<<K_TOT / 8, 256>>>(cb);                     // #2
    cvt_z_kernel<<<dim3(D_ / 32, HW_ / 32, 16), dim3(32, 8)>>>(z); // #3

    vq_mma_kernel<<<N_TOT / 128, 512, SM_TOTAL>>>();            // #4 (profiled)

    rescore_kernel<<<N_TOT / 8, 256>>>(z, cb, out_idx);         // #5

    gather_loss<<<ZQ_ELEMS / 256, 256>>>(z, cb, out_zq);        // #6

    finalize_loss<<<1, 1024>>>(out_loss);                       // #7
}